// round 11
// baseline (speedup 1.0000x reference)
#include <cuda_runtime.h>
#include <cstdint>

#define KTAG 64
#define BTOT 1024
#define TLEN 512
#define START_TAG 62
#define FWD_GRID (BTOT / 8)   // 128 blocks x 4 warps x 2 rows = 1024

// Scratch (allocation-free rule: __device__ globals)
__device__ float g_res[BTOT];   // forward_score[b] - gold_score[b]
__device__ int   g_cnt = 0;

typedef unsigned long long ull;

__device__ __forceinline__ ull pk2(float x, float y) {
    return (ull)__float_as_uint(x) | ((ull)__float_as_uint(y) << 32);
}
__device__ __forceinline__ float lo2(ull v) { return __uint_as_float((unsigned)v); }
__device__ __forceinline__ float hi2(ull v) { return __uint_as_float((unsigned)(v >> 32)); }
__device__ __forceinline__ float rcpf(float x) {
    float r; asm("rcp.approx.f32 %0, %1;" : "=f"(r) : "f"(x)); return r;
}

#define FMA2(acc, a, b) asm("fma.rn.f32x2 %0, %1, %2, %0;" : "+l"(acc) : "l"(a), "l"(b))
#define ADD2(d, a, b)   asm("add.rn.f32x2 %0, %1, %2;" : "=l"(d) : "l"(a), "l"(b))
#define MUL2(d, a, b)   asm("mul.rn.f32x2 %0, %1, %2;" : "=l"(d) : "l"(a), "l"(b))

// ---------------------------------------------------------------------------
// Fully fused CRF kernel, TWO batch rows per warp (R10 design + the race fix).
// Lane l owns tags 2l, 2l+1; E = exp(transitions) rows live in 124 regs and
// are SHARED by both rows — the two independent recurrence chains interleave
// so one row's serial tail (LDS/tree/STS) hides under the other row's FMA
// burst. Structurally zero pair (62,63) skipped. Deferred normalization by
// u = w[0] every 2nd step (exact bookkeeping — any positive u is exact).
// Gold path fused; last-block mean with PROPER ordering:
//   g_res stores -> __threadfence (all threads) -> __syncthreads -> counter.
// (R9/R10 lacked the __syncthreads: thread 0 could bump the counter before
//  warps 1-3 issued their g_res stores -> last block read stale rows. The
//  R10 failure was exactly 2/1024 rows stale.)
// ---------------------------------------------------------------------------
__global__ void __launch_bounds__(128, 1)
crf_fused_kernel(const float* __restrict__ feats,
                 const int* __restrict__ tags,
                 const float* __restrict__ trans,
                 float* __restrict__ out) {
    const int lane = threadIdx.x & 31;
    const int w    = threadIdx.x >> 5;          // warp within CTA (0..3)
    const int bA   = blockIdx.x * 8 + w * 2;    // batch row A
    const int bB   = bA + 1;                    // batch row B
    const int i0   = 2 * lane;
    const int i1   = 2 * lane + 1;

    __shared__ __align__(16) float sw_[4][2][2][KTAG];  // [warp][row][buf][tag]
    __shared__ __align__(16) int   stags[8][TLEN];

    // cache both rows' tags (int4 coalesced)
    {
        const int4* tgA = (const int4*)(tags + (size_t)bA * TLEN);
        const int4* tgB = (const int4*)(tags + (size_t)bB * TLEN);
        int4* sA = (int4*)stags[w * 2];
        int4* sB = (int4*)stags[w * 2 + 1];
#pragma unroll
        for (int j = lane; j < TLEN / 4; j += 32) { sA[j] = tgA[j]; sB[j] = tgB[j]; }
    }

    // E rows for tags i0, i1 (f32x2 packed over j); zero pair jj=31 skipped
    ull E0[31], E1[31];
#pragma unroll
    for (int jj = 0; jj < 31; jj++) {
        E0[jj] = pk2(__expf(trans[i0 * KTAG + 2 * jj]),
                     __expf(trans[i0 * KTAG + 2 * jj + 1]));
        E1[jj] = pk2(__expf(trans[i1 * KTAG + 2 * jj]),
                     __expf(trans[i1 * KTAG + 2 * jj + 1]));
    }

    const float* fbA = feats + (size_t)bA * TLEN * KTAG;
    const float* fbB = feats + (size_t)bB * TLEN * KTAG;

    // t = 1 exact for both rows: w1 = exp(trans[:,START] + feat1)
    float2 f1A = *(const float2*)(fbA + 1 * KTAG + i0);
    float2 f1B = *(const float2*)(fbB + 1 * KTAG + i0);
    {
        float t0 = trans[i0 * KTAG + START_TAG];
        float t1 = trans[i1 * KTAG + START_TAG];
        *(float2*)&sw_[w][0][0][i0] = make_float2(__expf(t0 + f1A.x), __expf(t1 + f1A.y));
        *(float2*)&sw_[w][1][0][i0] = make_float2(__expf(t0 + f1B.x), __expf(t1 + f1B.y));
    }
    float LA = 0.0f, LB = 0.0f;
    __syncwarp();                                 // stags + w1 visible

    // gold init (t = 1)
    int   ptA = stags[w * 2][0],     ptB = stags[w * 2 + 1][0];
    float goldA, goldB;
    {
        int ctA = stags[w * 2][1];
        int ctB = stags[w * 2 + 1][1];
        float gA = (ctA & 1) ? f1A.y : f1A.x;
        float gB = (ctB & 1) ? f1B.y : f1B.x;
        goldA = trans[ctA * KTAG + ptA] + __shfl_sync(0xffffffffu, gA, ctA >> 1);
        goldB = trans[ctB * KTAG + ptB] + __shfl_sync(0xffffffffu, gB, ctB >> 1);
        ptA = ctA; ptB = ctB;
    }

    // 2-deep feat pipelines per row: F[k] = feat(t = 2+k)
    float2 FA[2], FB[2];
#pragma unroll
    for (int k = 0; k < 2; k++) {
        FA[k] = *(const float2*)(fbA + (size_t)(2 + k) * KTAG + i0);
        FB[k] = *(const float2*)(fbB + (size_t)(2 + k) * KTAG + i0);
    }

#define GOLD_A(T, FX, FY)                                                     \
    {                                                                         \
        int ct = stags[w * 2][(T)];                                           \
        float gs = (ct & 1) ? (FY) : (FX);                                    \
        goldA += trans[ct * KTAG + ptA];                                      \
        goldA += __shfl_sync(0xffffffffu, gs, ct >> 1);                       \
        ptA = ct;                                                             \
    }
#define GOLD_B(T, FX, FY)                                                     \
    {                                                                         \
        int ct = stags[w * 2 + 1][(T)];                                       \
        float gs = (ct & 1) ? (FY) : (FX);                                    \
        goldB += trans[ct * KTAG + ptB];                                      \
        goldB += __shfl_sync(0xffffffffu, gs, ct >> 1);                       \
        ptB = ct;                                                             \
    }

    // one recurrence step for BOTH rows, interleaved; NORM -> renorm by w[0]
#define STEP2(T, eA0, eA1, eB0, eB1, NORM)                                    \
    {                                                                         \
        const int rbuf = (T) & 1;                                             \
        const ulonglong2* vpA = (const ulonglong2*)sw_[w][0][rbuf];           \
        const ulonglong2* vpB = (const ulonglong2*)sw_[w][1][rbuf];           \
        ulonglong2 vA0 = vpA[0];                                              \
        ulonglong2 vB0 = vpB[0];                                              \
        ull a0 = 0, a1 = 0, a2 = 0, a3 = 0, a4 = 0, a5 = 0, a6 = 0, a7 = 0;   \
        ull b0 = 0, b1 = 0, b2 = 0, b3 = 0, b4 = 0, b5 = 0, b6 = 0, b7 = 0;   \
        FMA2(a0, E0[0], vA0.x); FMA2(a1, E0[1], vA0.y);                       \
        FMA2(a2, E1[0], vA0.x); FMA2(a3, E1[1], vA0.y);                       \
        FMA2(b0, E0[0], vB0.x); FMA2(b1, E0[1], vB0.y);                       \
        FMA2(b2, E1[0], vB0.x); FMA2(b3, E1[1], vB0.y);                       \
        _Pragma("unroll")                                                     \
        for (int q = 1; q < 16; q++) {                                        \
            ulonglong2 vvA = vpA[q];                                          \
            ulonglong2 vvB = vpB[q];                                          \
            if (q == 15) {            /* pair (62,63) contributes zero */     \
                FMA2(a4, E0[30], vvA.x); FMA2(a6, E1[30], vvA.x);             \
                FMA2(b4, E0[30], vvB.x); FMA2(b6, E1[30], vvB.x);             \
            } else if (q & 1) {                                               \
                FMA2(a4, E0[2 * q], vvA.x); FMA2(a5, E0[2 * q + 1], vvA.y);   \
                FMA2(a6, E1[2 * q], vvA.x); FMA2(a7, E1[2 * q + 1], vvA.y);   \
                FMA2(b4, E0[2 * q], vvB.x); FMA2(b5, E0[2 * q + 1], vvB.y);   \
                FMA2(b6, E1[2 * q], vvB.x); FMA2(b7, E1[2 * q + 1], vvB.y);   \
            } else {                                                          \
                FMA2(a0, E0[2 * q], vvA.x); FMA2(a1, E0[2 * q + 1], vvA.y);   \
                FMA2(a2, E1[2 * q], vvA.x); FMA2(a3, E1[2 * q + 1], vvA.y);   \
                FMA2(b0, E0[2 * q], vvB.x); FMA2(b1, E0[2 * q + 1], vvB.y);   \
                FMA2(b2, E1[2 * q], vvB.x); FMA2(b3, E1[2 * q + 1], vvB.y);   \
            }                                                                 \
        }                                                                     \
        ull t0_, t1_, csA, dsA, csB, dsB, wnA, wnB;                           \
        ADD2(t0_, a0, a4); ADD2(t1_, a1, a5); ADD2(csA, t0_, t1_);            \
        ADD2(t0_, a2, a6); ADD2(t1_, a3, a7); ADD2(dsA, t0_, t1_);            \
        ADD2(t0_, b0, b4); ADD2(t1_, b1, b5); ADD2(csB, t0_, t1_);            \
        ADD2(t0_, b2, b6); ADD2(t1_, b3, b7); ADD2(dsB, t0_, t1_);            \
        float sA0 = lo2(csA) + hi2(csA);                                      \
        float sA1 = lo2(dsA) + hi2(dsA);                                      \
        float sB0 = lo2(csB) + hi2(csB);                                      \
        float sB1 = lo2(dsB) + hi2(dsB);                                      \
        if (NORM) {                                                           \
            float uA = lo2(vA0.x), uB = lo2(vB0.x);                           \
            float rA = rcpf(uA),   rB = rcpf(uB);                             \
            LA += __logf(uA);                                                 \
            LB += __logf(uB);                                                 \
            MUL2(wnA, pk2(sA0, sA1), pk2((eA0) * rA, (eA1) * rA));            \
            MUL2(wnB, pk2(sB0, sB1), pk2((eB0) * rB, (eB1) * rB));            \
        } else {                                                              \
            MUL2(wnA, pk2(sA0, sA1), pk2((eA0), (eA1)));                      \
            MUL2(wnB, pk2(sB0, sB1), pk2((eB0), (eB1)));                      \
        }                                                                     \
        *(ull*)&sw_[w][0][rbuf ^ 1][i0] = wnA;                                \
        *(ull*)&sw_[w][1][rbuf ^ 1][i0] = wnB;                                \
        __syncwarp();                                                         \
    }

    // main loop: t = 2 .. 509, 254 blocks of 2; norm on k == 1 (t odd)
    for (int kb = 0; kb < 254; kb++) {
#pragma unroll
        for (int k = 0; k < 2; k++) {
            const int t = 2 + 2 * kb + k;
            float fAx = FA[k].x, fAy = FA[k].y;
            float fBx = FB[k].x, fBy = FB[k].y;
            GOLD_A(t, fAx, fAy)
            GOLD_B(t, fBx, fBy)
            float eA0 = __expf(fAx), eA1 = __expf(fAy);
            float eB0 = __expf(fBx), eB1 = __expf(fBy);
            int tn = t + 2; if (tn > TLEN - 1) tn = TLEN - 1;
            FA[k] = *(const float2*)(fbA + (size_t)tn * KTAG + i0);
            FB[k] = *(const float2*)(fbB + (size_t)tn * KTAG + i0);
            if (k == 1) { STEP2(t, eA0, eA1, eB0, eB1, 1) }
            else        { STEP2(t, eA0, eA1, eB0, eB1, 0) }
        }
    }

    // t = 510 (feats in FA[0]/FB[0])
    {
        float fAx = FA[0].x, fAy = FA[0].y;
        float fBx = FB[0].x, fBy = FB[0].y;
        GOLD_A(510, fAx, fAy)
        GOLD_B(510, fBx, fBy)
        float eA0 = __expf(fAx), eA1 = __expf(fAy);
        float eB0 = __expf(fBx), eB1 = __expf(fBy);
        STEP2(510, eA0, eA1, eB0, eB1, 0)
    }

    // final step t = 511 (feats in FA[1]/FB[1])
    {
        float fAx = FA[1].x, fAy = FA[1].y;
        float fBx = FB[1].x, fBy = FB[1].y;
        GOLD_A(511, fAx, fAy)
        GOLD_B(511, fBx, fBy)
        float eA0 = __expf(fAx), eA1 = __expf(fAy);
        float eB0 = __expf(fBx), eB1 = __expf(fBy);
        const int rbuf = (TLEN - 1) & 1;
        const ulonglong2* vpA = (const ulonglong2*)sw_[w][0][rbuf];
        const ulonglong2* vpB = (const ulonglong2*)sw_[w][1][rbuf];
        ull a0 = 0, a1 = 0, a2 = 0, a3 = 0, a4 = 0, a5 = 0, a6 = 0, a7 = 0;
        ull b0 = 0, b1 = 0, b2 = 0, b3 = 0, b4 = 0, b5 = 0, b6 = 0, b7 = 0;
#pragma unroll
        for (int q = 0; q < 16; q++) {
            ulonglong2 vvA = vpA[q];
            ulonglong2 vvB = vpB[q];
            if (q == 15) {
                FMA2(a4, E0[30], vvA.x); FMA2(a6, E1[30], vvA.x);
                FMA2(b4, E0[30], vvB.x); FMA2(b6, E1[30], vvB.x);
            } else if (q & 1) {
                FMA2(a4, E0[2 * q], vvA.x); FMA2(a5, E0[2 * q + 1], vvA.y);
                FMA2(a6, E1[2 * q], vvA.x); FMA2(a7, E1[2 * q + 1], vvA.y);
                FMA2(b4, E0[2 * q], vvB.x); FMA2(b5, E0[2 * q + 1], vvB.y);
                FMA2(b6, E1[2 * q], vvB.x); FMA2(b7, E1[2 * q + 1], vvB.y);
            } else {
                FMA2(a0, E0[2 * q], vvA.x); FMA2(a1, E0[2 * q + 1], vvA.y);
                FMA2(a2, E1[2 * q], vvA.x); FMA2(a3, E1[2 * q + 1], vvA.y);
                FMA2(b0, E0[2 * q], vvB.x); FMA2(b1, E0[2 * q + 1], vvB.y);
                FMA2(b2, E1[2 * q], vvB.x); FMA2(b3, E1[2 * q + 1], vvB.y);
            }
        }
        ull t0_, t1_, csA, dsA, csB, dsB;
        ADD2(t0_, a0, a4); ADD2(t1_, a1, a5); ADD2(csA, t0_, t1_);
        ADD2(t0_, a2, a6); ADD2(t1_, a3, a7); ADD2(dsA, t0_, t1_);
        ADD2(t0_, b0, b4); ADD2(t1_, b1, b5); ADD2(csB, t0_, t1_);
        ADD2(t0_, b2, b6); ADD2(t1_, b3, b7); ADD2(dsB, t0_, t1_);
        float zA = (lo2(csA) + hi2(csA)) * eA0 + (lo2(dsA) + hi2(dsA)) * eA1;
        float zB = (lo2(csB) + hi2(csB)) * eB0 + (lo2(dsB) + hi2(dsB)) * eB1;
#pragma unroll
        for (int o = 16; o > 0; o >>= 1) {
            zA += __shfl_xor_sync(0xffffffffu, zA, o);
            zB += __shfl_xor_sync(0xffffffffu, zB, o);
        }
        if (lane == 0) {
            g_res[bA] = (LA + __logf(zA)) - goldA;
            g_res[bB] = (LB + __logf(zB)) - goldB;
        }
    }
#undef STEP2
#undef GOLD_A
#undef GOLD_B

    // ---- last-block mean reduction (RACE FIX) ----
    // Order: per-warp g_res stores -> __threadfence (every thread, so each
    // writer's store is fenced) -> __syncthreads (all warps' fenced stores
    // happen-before thread 0's counter bump) -> atomic counter.
    __threadfence();
    __syncthreads();
    __shared__ int is_last;
    if (threadIdx.x == 0) {
        int old = atomicAdd(&g_cnt, 1);
        is_last = (old == FWD_GRID - 1) ? 1 : 0;
    }
    __syncthreads();
    if (is_last) {
        __threadfence();
        __shared__ float sh[4];
        const int tid = threadIdx.x;
        float acc = 0.0f;
        for (int x = tid; x < BTOT; x += 128) acc += g_res[x];
#pragma unroll
        for (int o = 16; o > 0; o >>= 1)
            acc += __shfl_xor_sync(0xffffffffu, acc, o);
        if ((tid & 31) == 0) sh[tid >> 5] = acc;
        __syncthreads();
        if (tid == 0) {
            out[0] = (sh[0] + sh[1] + sh[2] + sh[3]) / (float)BTOT;
            g_cnt  = 0;   // reset for next graph replay
        }
    }
}

extern "C" void kernel_launch(void* const* d_in, const int* in_sizes, int n_in,
                              void* d_out, int out_size) {
    const float* feats = (const float*)d_in[0];
    const int*   tags  = (const int*)d_in[1];
    const float* trans = (const float*)d_in[2];
    float* out = (float*)d_out;

    crf_fused_kernel<<<FWD_GRID, 128>>>(feats, tags, trans, out);
}

// round 12
// speedup vs baseline: 1.1701x; 1.1701x over previous
#include <cuda_runtime.h>
#include <cstdint>

#define KTAG 64
#define BTOT 1024
#define TLEN 512
#define START_TAG 62
#define FWD_GRID (BTOT / 4)   // 256 blocks x 4 warps = 1024 rows

// Scratch (allocation-free rule: __device__ globals)
__device__ float g_res[BTOT];   // forward_score[b] - gold_score[b]
__device__ int   g_cnt = 0;

typedef unsigned long long ull;

__device__ __forceinline__ ull pk2(float x, float y) {
    return (ull)__float_as_uint(x) | ((ull)__float_as_uint(y) << 32);
}
__device__ __forceinline__ float lo2(ull v) { return __uint_as_float((unsigned)v); }
__device__ __forceinline__ float hi2(ull v) { return __uint_as_float((unsigned)(v >> 32)); }
__device__ __forceinline__ float rcpf(float x) {
    float r; asm("rcp.approx.f32 %0, %1;" : "=f"(r) : "f"(x)); return r;
}

#define FMA2(acc, a, b) asm("fma.rn.f32x2 %0, %1, %2, %0;" : "+l"(acc) : "l"(a), "l"(b))
#define ADD2(d, a, b)   asm("add.rn.f32x2 %0, %1, %2;" : "=l"(d) : "l"(a), "l"(b))
#define MUL2(d, a, b)   asm("mul.rn.f32x2 %0, %1, %2;" : "=l"(d) : "l"(a), "l"(b))

// ---------------------------------------------------------------------------
// Fully fused CRF kernel (R9 design — the measured optimum — plus the
// reduction-ordering fix validated in R11).
// One warp per batch row; lane l owns tags 2l, 2l+1 and their
// E = exp(transitions) rows (f32x2-packed regs; structurally zero pair
// (62,63) skipped: w[62]==0 for t>=2 and E[:,63]==0).
// Per step: s_i = sum_j E[i,j] w_j (16 LDS.128 + 60 FMA2, 8 chains);
// w' = s * exp(f_t), renormalized by u = w[0] every 4th step (exact
// bookkeeping; bounded growth stays well inside fp32 range). Feat pipeline
// 4 deep (MLP=4). Gold path fused: tags cached in smem; feats[t][ct]
// shuffled from the lane holding it; trans[ct,pt] from L1.
// Last-block mean reduction with PROPER ordering:
//   g_res stores -> __threadfence (all threads) -> __syncthreads -> counter.
// ---------------------------------------------------------------------------
__global__ void __launch_bounds__(128, 2)
crf_fused_kernel(const float* __restrict__ feats,
                 const int* __restrict__ tags,
                 const float* __restrict__ trans,
                 float* __restrict__ out) {
    const int lane = threadIdx.x & 31;
    const int w    = threadIdx.x >> 5;          // row within CTA (0..3)
    const int b    = blockIdx.x * 4 + w;
    const int i0   = 2 * lane;
    const int i1   = 2 * lane + 1;

    __shared__ __align__(16) float sw_[4][2][KTAG];
    __shared__ __align__(16) int   stags[4][TLEN];

    // cache this row's tags (int4 coalesced)
    {
        const int4* tg4 = (const int4*)(tags + (size_t)b * TLEN);
        int4* st4 = (int4*)stags[w];
#pragma unroll
        for (int j = lane; j < TLEN / 4; j += 32) st4[j] = tg4[j];
    }

    // E rows for tags i0, i1 (f32x2 packed over j); pair jj=31 skipped
    ull E0[31], E1[31];
#pragma unroll
    for (int jj = 0; jj < 31; jj++) {
        E0[jj] = pk2(__expf(trans[i0 * KTAG + 2 * jj]),
                     __expf(trans[i0 * KTAG + 2 * jj + 1]));
        E1[jj] = pk2(__expf(trans[i1 * KTAG + 2 * jj]),
                     __expf(trans[i1 * KTAG + 2 * jj + 1]));
    }

    const float* fb = feats + (size_t)b * TLEN * KTAG;

    // t = 1 exact: w1 = exp(trans[:,START] + feat1)
    float2 f1 = *(const float2*)(fb + 1 * KTAG + i0);
    float a0 = trans[i0 * KTAG + START_TAG] + f1.x;
    float a1 = trans[i1 * KTAG + START_TAG] + f1.y;
    *(float2*)&sw_[w][0][i0] = make_float2(__expf(a0), __expf(a1));
    float L = 0.0f;
    __syncwarp();                                 // stags + w1 visible

    // gold init (t = 1): trans[ct,pt] + feats[1][ct] via shfl
    int   pt = stags[w][0];
    float gold;
    {
        int ct = stags[w][1];
        float gs = (ct & 1) ? f1.y : f1.x;
        gold = trans[ct * KTAG + pt] + __shfl_sync(0xffffffffu, gs, ct >> 1);
        pt = ct;
    }

    // 4-deep feat pipeline: F[k] = feat(t = 2+k) raw
    float2 F[4];
#pragma unroll
    for (int k = 0; k < 4; k++)
        F[k] = *(const float2*)(fb + (size_t)(2 + k) * KTAG + i0);

    // gold accumulation for step T, raw feat pair (FX, FY)
#define GOLD_ACC(T, FX, FY)                                                   \
    {                                                                         \
        int ct = stags[w][(T)];                                               \
        float gs = (ct & 1) ? (FY) : (FX);                                    \
        gold += trans[ct * KTAG + pt];                                        \
        gold += __shfl_sync(0xffffffffu, gs, ct >> 1);                        \
        pt = ct;                                                              \
    }

    // one recurrence step; NORM = 1 -> renormalize by u = w[0]
#define STEP_BODY(T, EFC0, EFC1, NORM)                                        \
    {                                                                         \
        const int rbuf = (T) & 1;                                             \
        const ulonglong2* vp = (const ulonglong2*)sw_[w][rbuf];               \
        ulonglong2 v0 = vp[0];                                                \
        ull c0 = 0, c1 = 0, c2 = 0, c3 = 0;                                   \
        ull d0 = 0, d1 = 0, d2 = 0, d3 = 0;                                   \
        FMA2(c0, E0[0], v0.x); FMA2(c1, E0[1], v0.y);                         \
        FMA2(d0, E1[0], v0.x); FMA2(d1, E1[1], v0.y);                         \
        _Pragma("unroll")                                                     \
        for (int q = 1; q < 16; q++) {                                        \
            ulonglong2 vv = vp[q];                                            \
            if (q == 15) {            /* pair (62,63) contributes zero */     \
                FMA2(c2, E0[30], vv.x);                                       \
                FMA2(d2, E1[30], vv.x);                                       \
            } else if (q & 1) {                                               \
                FMA2(c2, E0[2 * q], vv.x); FMA2(c3, E0[2 * q + 1], vv.y);     \
                FMA2(d2, E1[2 * q], vv.x); FMA2(d3, E1[2 * q + 1], vv.y);     \
            } else {                                                          \
                FMA2(c0, E0[2 * q], vv.x); FMA2(c1, E0[2 * q + 1], vv.y);     \
                FMA2(d0, E1[2 * q], vv.x); FMA2(d1, E1[2 * q + 1], vv.y);     \
            }                                                                 \
        }                                                                     \
        ull cA, cB, cs, dA, dB, ds, wn;                                       \
        ADD2(cA, c0, c2); ADD2(cB, c1, c3); ADD2(cs, cA, cB);                 \
        ADD2(dA, d0, d2); ADD2(dB, d1, d3); ADD2(ds, dA, dB);                 \
        float s0 = lo2(cs) + hi2(cs);                                         \
        float s1 = lo2(ds) + hi2(ds);                                         \
        if (NORM) {                                                           \
            float uu = lo2(v0.x);                                             \
            float r  = rcpf(uu);                                              \
            L += __logf(uu);                                                  \
            MUL2(wn, pk2(s0, s1), pk2((EFC0) * r, (EFC1) * r));               \
        } else {                                                              \
            MUL2(wn, pk2(s0, s1), pk2((EFC0), (EFC1)));                       \
        }                                                                     \
        *(ull*)&sw_[w][rbuf ^ 1][i0] = wn;                                    \
        __syncwarp();                                                         \
    }

    // main loop: t = 2 .. 509, 127 blocks of 4 (MLP=4); norm at k == 3
    for (int kb = 0; kb < 127; kb++) {
#pragma unroll
        for (int k = 0; k < 4; k++) {
            const int t = 2 + 4 * kb + k;
            float fx = F[k].x, fy = F[k].y;
            GOLD_ACC(t, fx, fy)
            float efc0 = __expf(fx);
            float efc1 = __expf(fy);
            int tn = t + 4; if (tn > TLEN - 1) tn = TLEN - 1;
            F[k] = *(const float2*)(fb + (size_t)tn * KTAG + i0);
            if (k == 3) { STEP_BODY(t, efc0, efc1, 1) }
            else        { STEP_BODY(t, efc0, efc1, 0) }
        }
    }

    // t = 510 (feat in F[0])
    {
        float fx = F[0].x, fy = F[0].y;
        GOLD_ACC(510, fx, fy)
        float efc0 = __expf(fx);
        float efc1 = __expf(fy);
        STEP_BODY(510, efc0, efc1, 0)
    }

    // final step t = 511 (feat in F[1]): forward = L + log(sum_i s_i*exp(f_i))
    {
        float fx = F[1].x, fy = F[1].y;
        GOLD_ACC(511, fx, fy)
        float ef0 = __expf(fx);
        float ef1 = __expf(fy);
        const int rbuf = (TLEN - 1) & 1;
        const ulonglong2* vp = (const ulonglong2*)sw_[w][rbuf];
        ull c0 = 0, c1 = 0, c2 = 0, c3 = 0;
        ull d0 = 0, d1 = 0, d2 = 0, d3 = 0;
#pragma unroll
        for (int q = 0; q < 16; q++) {
            ulonglong2 vv = vp[q];
            if (q == 15) {
                FMA2(c2, E0[30], vv.x);
                FMA2(d2, E1[30], vv.x);
            } else if (q & 1) {
                FMA2(c2, E0[2 * q], vv.x); FMA2(c3, E0[2 * q + 1], vv.y);
                FMA2(d2, E1[2 * q], vv.x); FMA2(d3, E1[2 * q + 1], vv.y);
            } else {
                FMA2(c0, E0[2 * q], vv.x); FMA2(c1, E0[2 * q + 1], vv.y);
                FMA2(d0, E1[2 * q], vv.x); FMA2(d1, E1[2 * q + 1], vv.y);
            }
        }
        ull cA, cB, cs, dA, dB, ds;
        ADD2(cA, c0, c2); ADD2(cB, c1, c3); ADD2(cs, cA, cB);
        ADD2(dA, d0, d2); ADD2(dB, d1, d3); ADD2(ds, dA, dB);
        float s0 = lo2(cs) + hi2(cs);
        float s1 = lo2(ds) + hi2(ds);
        float z = s0 * ef0 + s1 * ef1;
#pragma unroll
        for (int o = 16; o > 0; o >>= 1)
            z += __shfl_xor_sync(0xffffffffu, z, o);
        if (lane == 0) g_res[b] = (L + __logf(z)) - gold;
    }
#undef STEP_BODY
#undef GOLD_ACC

    // ---- last-block mean reduction (RACE FIX, validated in R11) ----
    // Order: per-warp g_res stores -> __threadfence (every thread, so each
    // writer's store is fenced) -> __syncthreads (all warps' fenced stores
    // happen-before thread 0's counter bump) -> atomic counter.
    __threadfence();
    __syncthreads();
    __shared__ int is_last;
    if (threadIdx.x == 0) {
        int old = atomicAdd(&g_cnt, 1);
        is_last = (old == FWD_GRID - 1) ? 1 : 0;
    }
    __syncthreads();
    if (is_last) {
        __threadfence();
        __shared__ float sh[4];
        const int tid = threadIdx.x;
        float acc = 0.0f;
        for (int x = tid; x < BTOT; x += 128) acc += g_res[x];
#pragma unroll
        for (int o = 16; o > 0; o >>= 1)
            acc += __shfl_xor_sync(0xffffffffu, acc, o);
        if ((tid & 31) == 0) sh[tid >> 5] = acc;
        __syncthreads();
        if (tid == 0) {
            out[0] = (sh[0] + sh[1] + sh[2] + sh[3]) / (float)BTOT;
            g_cnt  = 0;   // reset for next graph replay
        }
    }
}

extern "C" void kernel_launch(void* const* d_in, const int* in_sizes, int n_in,
                              void* d_out, int out_size) {
    const float* feats = (const float*)d_in[0];
    const int*   tags  = (const int*)d_in[1];
    const float* trans = (const float*)d_in[2];
    float* out = (float*)d_out;

    crf_fused_kernel<<<FWD_GRID, 128>>>(feats, tags, trans, out);
}

// round 13
// speedup vs baseline: 1.2115x; 1.0354x over previous
#include <cuda_runtime.h>
#include <cstdint>

#define KTAG 64
#define BTOT 1024
#define TLEN 512
#define START_TAG 62
#define FWD_GRID (BTOT / 4)   // 256 blocks x 4 warps = 1024 rows

// Scratch (allocation-free rule: __device__ globals)
__device__ float g_res[BTOT];   // forward_score[b] - gold_score[b]
__device__ int   g_cnt = 0;

typedef unsigned long long ull;

__device__ __forceinline__ ull pk2(float x, float y) {
    return (ull)__float_as_uint(x) | ((ull)__float_as_uint(y) << 32);
}
__device__ __forceinline__ float lo2(ull v) { return __uint_as_float((unsigned)v); }
__device__ __forceinline__ float hi2(ull v) { return __uint_as_float((unsigned)(v >> 32)); }
__device__ __forceinline__ float rcpf(float x) {
    float r; asm("rcp.approx.f32 %0, %1;" : "=f"(r) : "f"(x)); return r;
}

#define FMA2(acc, a, b) asm("fma.rn.f32x2 %0, %1, %2, %0;" : "+l"(acc) : "l"(a), "l"(b))
#define ADD2(d, a, b)   asm("add.rn.f32x2 %0, %1, %2;" : "=l"(d) : "l"(a), "l"(b))
#define MUL2(d, a, b)   asm("mul.rn.f32x2 %0, %1, %2;" : "=l"(d) : "l"(a), "l"(b))

// ---------------------------------------------------------------------------
// Fully fused CRF kernel (R12 base) + micro-package:
//  - trans table copied to smem once: the per-step gold lookup becomes an LDS
//    (the streaming feats wash L1, so the old per-step LDG was often an
//    L2 round trip of ~250 cyc).
//  - tags cached as uint8 in smem (values < 64).
//  - packed epilogue tail: (s0,s1) assembled with one ADD2 from chain-sum
//    halves instead of scalar FADDs.
// One warp per batch row; lane l owns tags 2l,2l+1 + E-rows in 124 regs;
// deferred normalization by u = w[0] every 4th step (exact bookkeeping);
// 4-deep feat prefetch (MLP=4); zero pair (62,63) skipped; gold fused;
// last-block mean with the R11-validated ordering fix.
// ---------------------------------------------------------------------------
__global__ void __launch_bounds__(128, 2)
crf_fused_kernel(const float* __restrict__ feats,
                 const int* __restrict__ tags,
                 const float* __restrict__ trans,
                 float* __restrict__ out) {
    const int lane = threadIdx.x & 31;
    const int w    = threadIdx.x >> 5;          // row within CTA (0..3)
    const int b    = blockIdx.x * 4 + w;
    const int i0   = 2 * lane;
    const int i1   = 2 * lane + 1;

    __shared__ __align__(16) float         sw_[4][2][KTAG];
    __shared__ __align__(16) float         strans[KTAG * KTAG];   // 16 KB
    __shared__ __align__(16) unsigned char stagsu[4][TLEN];       // 2 KB

    // copy trans to smem (float4 coalesced, whole CTA)
    {
        const float4* t4 = (const float4*)trans;
        float4* s4 = (float4*)strans;
#pragma unroll
        for (int j = threadIdx.x; j < (KTAG * KTAG) / 4; j += 128) s4[j] = t4[j];
    }

    // cache this row's tags as uint8 (int4 coalesced loads)
    {
        const int4* tg4 = (const int4*)(tags + (size_t)b * TLEN);
        uchar4* st4 = (uchar4*)stagsu[w];
#pragma unroll
        for (int j = lane; j < TLEN / 4; j += 32) {
            int4 v = tg4[j];
            st4[j] = make_uchar4((unsigned char)v.x, (unsigned char)v.y,
                                 (unsigned char)v.z, (unsigned char)v.w);
        }
    }

    // E rows for tags i0, i1 (f32x2 packed over j); pair jj=31 skipped
    ull E0[31], E1[31];
#pragma unroll
    for (int jj = 0; jj < 31; jj++) {
        E0[jj] = pk2(__expf(trans[i0 * KTAG + 2 * jj]),
                     __expf(trans[i0 * KTAG + 2 * jj + 1]));
        E1[jj] = pk2(__expf(trans[i1 * KTAG + 2 * jj]),
                     __expf(trans[i1 * KTAG + 2 * jj + 1]));
    }

    const float* fb = feats + (size_t)b * TLEN * KTAG;

    // t = 1 exact: w1 = exp(trans[:,START] + feat1)
    float2 f1 = *(const float2*)(fb + 1 * KTAG + i0);
    float a0 = trans[i0 * KTAG + START_TAG] + f1.x;
    float a1 = trans[i1 * KTAG + START_TAG] + f1.y;
    *(float2*)&sw_[w][0][i0] = make_float2(__expf(a0), __expf(a1));
    float L = 0.0f;
    __syncthreads();                              // strans + stags + w1 visible

    // gold init (t = 1): trans[ct,pt] + feats[1][ct] via shfl
    int   pt = stagsu[w][0];
    float gold;
    {
        int ct = stagsu[w][1];
        float gs = (ct & 1) ? f1.y : f1.x;
        gold = strans[ct * KTAG + pt] + __shfl_sync(0xffffffffu, gs, ct >> 1);
        pt = ct;
    }

    // 4-deep feat pipeline: F[k] = feat(t = 2+k) raw
    float2 F[4];
#pragma unroll
    for (int k = 0; k < 4; k++)
        F[k] = *(const float2*)(fb + (size_t)(2 + k) * KTAG + i0);

    // gold accumulation for step T, raw feat pair (FX, FY) — all smem now
#define GOLD_ACC(T, FX, FY)                                                   \
    {                                                                         \
        int ct = stagsu[w][(T)];                                              \
        float gs = (ct & 1) ? (FY) : (FX);                                    \
        gold += strans[ct * KTAG + pt];                                       \
        gold += __shfl_sync(0xffffffffu, gs, ct >> 1);                        \
        pt = ct;                                                              \
    }

    // one recurrence step; NORM = 1 -> renormalize by u = w[0]
#define STEP_BODY(T, EFC0, EFC1, NORM)                                        \
    {                                                                         \
        const int rbuf = (T) & 1;                                             \
        const ulonglong2* vp = (const ulonglong2*)sw_[w][rbuf];               \
        ulonglong2 v0 = vp[0];                                                \
        ull c0 = 0, c1 = 0, c2 = 0, c3 = 0;                                   \
        ull d0 = 0, d1 = 0, d2 = 0, d3 = 0;                                   \
        FMA2(c0, E0[0], v0.x); FMA2(c1, E0[1], v0.y);                         \
        FMA2(d0, E1[0], v0.x); FMA2(d1, E1[1], v0.y);                         \
        _Pragma("unroll")                                                     \
        for (int q = 1; q < 16; q++) {                                        \
            ulonglong2 vv = vp[q];                                            \
            if (q == 15) {            /* pair (62,63) contributes zero */     \
                FMA2(c2, E0[30], vv.x);                                       \
                FMA2(d2, E1[30], vv.x);                                       \
            } else if (q & 1) {                                               \
                FMA2(c2, E0[2 * q], vv.x); FMA2(c3, E0[2 * q + 1], vv.y);     \
                FMA2(d2, E1[2 * q], vv.x); FMA2(d3, E1[2 * q + 1], vv.y);     \
            } else {                                                          \
                FMA2(c0, E0[2 * q], vv.x); FMA2(c1, E0[2 * q + 1], vv.y);     \
                FMA2(d0, E1[2 * q], vv.x); FMA2(d1, E1[2 * q + 1], vv.y);     \
            }                                                                 \
        }                                                                     \
        ull cA, cB, cs, dA, dB, ds, sp, sq, sv2, mm, wn;                      \
        ADD2(cA, c0, c2); ADD2(cB, c1, c3); ADD2(cs, cA, cB);                 \
        ADD2(dA, d0, d2); ADD2(dB, d1, d3); ADD2(ds, dA, dB);                 \
        sp = pk2(lo2(cs), lo2(ds));                                           \
        sq = pk2(hi2(cs), hi2(ds));                                           \
        ADD2(sv2, sp, sq);                        /* (s0, s1) packed */       \
        if (NORM) {                                                           \
            float uu = lo2(v0.x);                                             \
            float r  = rcpf(uu);                                              \
            L += __logf(uu);                                                  \
            mm = pk2((EFC0) * r, (EFC1) * r);                                 \
        } else {                                                              \
            mm = pk2((EFC0), (EFC1));                                         \
        }                                                                     \
        MUL2(wn, sv2, mm);                                                    \
        *(ull*)&sw_[w][rbuf ^ 1][i0] = wn;                                    \
        __syncwarp();                                                         \
    }

    // main loop: t = 2 .. 509, 127 blocks of 4 (MLP=4); norm at k == 3
    for (int kb = 0; kb < 127; kb++) {
#pragma unroll
        for (int k = 0; k < 4; k++) {
            const int t = 2 + 4 * kb + k;
            float fx = F[k].x, fy = F[k].y;
            GOLD_ACC(t, fx, fy)
            float efc0 = __expf(fx);
            float efc1 = __expf(fy);
            int tn = t + 4; if (tn > TLEN - 1) tn = TLEN - 1;
            F[k] = *(const float2*)(fb + (size_t)tn * KTAG + i0);
            if (k == 3) { STEP_BODY(t, efc0, efc1, 1) }
            else        { STEP_BODY(t, efc0, efc1, 0) }
        }
    }

    // t = 510 (feat in F[0])
    {
        float fx = F[0].x, fy = F[0].y;
        GOLD_ACC(510, fx, fy)
        float efc0 = __expf(fx);
        float efc1 = __expf(fy);
        STEP_BODY(510, efc0, efc1, 0)
    }

    // final step t = 511 (feat in F[1]): forward = L + log(sum_i s_i*exp(f_i))
    {
        float fx = F[1].x, fy = F[1].y;
        GOLD_ACC(511, fx, fy)
        float ef0 = __expf(fx);
        float ef1 = __expf(fy);
        const int rbuf = (TLEN - 1) & 1;
        const ulonglong2* vp = (const ulonglong2*)sw_[w][rbuf];
        ull c0 = 0, c1 = 0, c2 = 0, c3 = 0;
        ull d0 = 0, d1 = 0, d2 = 0, d3 = 0;
#pragma unroll
        for (int q = 0; q < 16; q++) {
            ulonglong2 vv = vp[q];
            if (q == 15) {
                FMA2(c2, E0[30], vv.x);
                FMA2(d2, E1[30], vv.x);
            } else if (q & 1) {
                FMA2(c2, E0[2 * q], vv.x); FMA2(c3, E0[2 * q + 1], vv.y);
                FMA2(d2, E1[2 * q], vv.x); FMA2(d3, E1[2 * q + 1], vv.y);
            } else {
                FMA2(c0, E0[2 * q], vv.x); FMA2(c1, E0[2 * q + 1], vv.y);
                FMA2(d0, E1[2 * q], vv.x); FMA2(d1, E1[2 * q + 1], vv.y);
            }
        }
        ull cA, cB, cs, dA, dB, ds;
        ADD2(cA, c0, c2); ADD2(cB, c1, c3); ADD2(cs, cA, cB);
        ADD2(dA, d0, d2); ADD2(dB, d1, d3); ADD2(ds, dA, dB);
        float s0 = lo2(cs) + hi2(cs);
        float s1 = lo2(ds) + hi2(ds);
        float z = s0 * ef0 + s1 * ef1;
#pragma unroll
        for (int o = 16; o > 0; o >>= 1)
            z += __shfl_xor_sync(0xffffffffu, z, o);
        if (lane == 0) g_res[b] = (L + __logf(z)) - gold;
    }
#undef STEP_BODY
#undef GOLD_ACC

    // ---- last-block mean reduction (R11-validated ordering) ----
    // per-warp g_res stores -> __threadfence (every thread) -> __syncthreads
    // -> atomic counter. Counter self-resets for graph replay.
    __threadfence();
    __syncthreads();
    __shared__ int is_last;
    if (threadIdx.x == 0) {
        int old = atomicAdd(&g_cnt, 1);
        is_last = (old == FWD_GRID - 1) ? 1 : 0;
    }
    __syncthreads();
    if (is_last) {
        __threadfence();
        __shared__ float sh[4];
        const int tid = threadIdx.x;
        float acc = 0.0f;
        for (int x = tid; x < BTOT; x += 128) acc += g_res[x];
#pragma unroll
        for (int o = 16; o > 0; o >>= 1)
            acc += __shfl_xor_sync(0xffffffffu, acc, o);
        if ((tid & 31) == 0) sh[tid >> 5] = acc;
        __syncthreads();
        if (tid == 0) {
            out[0] = (sh[0] + sh[1] + sh[2] + sh[3]) / (float)BTOT;
            g_cnt  = 0;   // reset for next graph replay
        }
    }
}

extern "C" void kernel_launch(void* const* d_in, const int* in_sizes, int n_in,
                              void* d_out, int out_size) {
    const float* feats = (const float*)d_in[0];
    const int*   tags  = (const int*)d_in[1];
    const float* trans = (const float*)d_in[2];
    float* out = (float*)d_out;

    crf_fused_kernel<<<FWD_GRID, 128>>>(feats, tags, trans, out);
}